// round 15
// baseline (speedup 1.0000x reference)
#include <cuda_runtime.h>
#include <cuda_bf16.h>
#include <cstdint>

#define BB 8
#define SS 1024
#define DD 512
#define HH 8
#define DH 64
#define L2P 2047
#define SCALE 0.125f
#define MROWS (BB*SS)      // 8192
#define PROWS (BB*L2P)     // 16376

// ---------------- scratch ----------------
__device__ __nv_bfloat16 g_xqh[MROWS*DD], g_xql[MROWS*DD];
__device__ __nv_bfloat16 g_xkh[MROWS*DD], g_xkl[MROWS*DD];
__device__ __nv_bfloat16 g_xvh[MROWS*DD], g_xvl[MROWS*DD];
__device__ __nv_bfloat16 g_xph[PROWS*DD], g_xpl[PROWS*DD];
__device__ __nv_bfloat16 g_wh[5*DD*DD], g_wl[5*DD*DD];
__device__ __nv_bfloat16 g_qh[MROWS*DD],  g_ql[MROWS*DD];
__device__ __nv_bfloat16 g_kh[MROWS*DD],  g_kl[MROWS*DD];
__device__ __nv_bfloat16 g_vh[MROWS*DD],  g_vl[MROWS*DD];
__device__ __nv_bfloat16 g_ph[(PROWS+8)*DD], g_pl[(PROWS+8)*DD];
__device__ __nv_bfloat16 g_ch[MROWS*DD], g_cl[MROWS*DD];
__device__ float g_uk[BB*HH*SS];
__device__ float g_vp[BB*HH*L2P + 64];

// ---------------- helpers ----------------
__device__ __forceinline__ void split_pair(float x0, float x1, uint32_t& h, uint32_t& l) {
    __nv_bfloat162 hh = __floats2bfloat162_rn(x0, x1);
    float r0 = x0 - __bfloat162float(hh.x);
    float r1 = x1 - __bfloat162float(hh.y);
    __nv_bfloat162 ll = __floats2bfloat162_rn(r0, r1);
    h = *reinterpret_cast<uint32_t*>(&hh);
    l = *reinterpret_cast<uint32_t*>(&ll);
}
__device__ __forceinline__ float2 unsplit(uint32_t h, uint32_t l) {
    __nv_bfloat162 hh = *reinterpret_cast<__nv_bfloat162*>(&h);
    __nv_bfloat162 ll = *reinterpret_cast<__nv_bfloat162*>(&l);
    return make_float2(__bfloat162float(hh.x) + __bfloat162float(ll.x),
                       __bfloat162float(hh.y) + __bfloat162float(ll.y));
}
__device__ __forceinline__ void mma16816(float d[4], const uint32_t a[4], const uint32_t b[2]) {
    asm volatile(
        "mma.sync.aligned.m16n8k16.row.col.f32.bf16.bf16.f32 "
        "{%0,%1,%2,%3}, {%4,%5,%6,%7}, {%8,%9}, {%0,%1,%2,%3};\n"
        : "+f"(d[0]), "+f"(d[1]), "+f"(d[2]), "+f"(d[3])
        : "r"(a[0]), "r"(a[1]), "r"(a[2]), "r"(a[3]), "r"(b[0]), "r"(b[1]));
}
__device__ __forceinline__ void mma3(float d[4], const uint32_t ah[4], const uint32_t al[4],
                                     const uint32_t bh[2], const uint32_t bl[2]) {
    mma16816(d, ah, bh);
    mma16816(d, ah, bl);
    mma16816(d, al, bh);
}
__device__ __forceinline__ void ldsm4(uint32_t r[4], uint32_t addr) {
    asm volatile("ldmatrix.sync.aligned.m8n8.x4.shared.b16 {%0,%1,%2,%3},[%4];"
        : "=r"(r[0]), "=r"(r[1]), "=r"(r[2]), "=r"(r[3]) : "r"(addr));
}
__device__ __forceinline__ void ldsm4t(uint32_t r[4], uint32_t addr) {
    asm volatile("ldmatrix.sync.aligned.m8n8.x4.trans.shared.b16 {%0,%1,%2,%3},[%4];"
        : "=r"(r[0]), "=r"(r[1]), "=r"(r[2]), "=r"(r[3]) : "r"(addr));
}
__device__ __forceinline__ void cp16(uint32_t dst, const void* src, bool pred) {
    int sz = pred ? 16 : 0;
    asm volatile("cp.async.cg.shared.global [%0],[%1],16,%2;\n"
        :: "r"(dst), "l"(src), "r"(sz));
}
__device__ __forceinline__ void cp4(uint32_t dst, const void* src) {
    asm volatile("cp.async.ca.shared.global [%0],[%1],4;\n" :: "r"(dst), "l"(src));
}
__device__ __forceinline__ void cpcommit() { asm volatile("cp.async.commit_group;\n"); }
template<int N> __device__ __forceinline__ void cpwait() {
    asm volatile("cp.async.wait_group %0;\n" :: "n"(N));
}

// ---------------- merged split prepass (inputs + weights, one launch) ----------------
#define C_Q  (MROWS*DD/4)
#define C_K  (2*C_Q)
#define C_V  (3*C_Q)
#define C_P  (C_V + PROWS*DD/4)
#define C_W  (C_P + 5*(DD*DD/4))
__global__ __launch_bounds__(256) void split_all(const float4* __restrict__ q,
                                                 const float4* __restrict__ k,
                                                 const float4* __restrict__ v,
                                                 const float4* __restrict__ p,
                                                 const float4* __restrict__ W0,
                                                 const float4* __restrict__ W1,
                                                 const float4* __restrict__ W2,
                                                 const float4* __restrict__ W3,
                                                 const float4* __restrict__ W4) {
    long i = (long)blockIdx.x * 256 + threadIdx.x;
    const float4* src; uint32_t *hi, *lo; long off;
    if (i < C_Q)      { src = q; hi = (uint32_t*)g_xqh; lo = (uint32_t*)g_xql; off = i; }
    else if (i < C_K) { src = k; hi = (uint32_t*)g_xkh; lo = (uint32_t*)g_xkl; off = i - C_Q; }
    else if (i < C_V) { src = v; hi = (uint32_t*)g_xvh; lo = (uint32_t*)g_xvl; off = i - C_K; }
    else if (i < C_P) { src = p; hi = (uint32_t*)g_xph; lo = (uint32_t*)g_xpl; off = i - C_V; }
    else if (i < C_W) {
        long wi = i - C_P;
        int z = (int)(wi / (DD*DD/4));
        off = wi - (long)z * (DD*DD/4);
        src = (z == 0) ? W0 : (z == 1) ? W1 : (z == 2) ? W2 : (z == 3) ? W3 : W4;
        hi = (uint32_t*)g_wh + (size_t)z * (DD*DD/2);
        lo = (uint32_t*)g_wl + (size_t)z * (DD*DD/2);
    } else return;
    float4 val = src[off];
    uint32_t h0, l0, h1, l1;
    split_pair(val.x, val.y, h0, l0);
    split_pair(val.z, val.w, h1, l1);
    hi[2*off] = h0; hi[2*off+1] = h1;
    lo[2*off] = l0; lo[2*off+1] = l1;
}

// ---------------- merged bias GEMV (z=0: u.k ; z=1: v.p) ----------------
__global__ __launch_bounds__(256) void biasdot2(const float* __restrict__ ub,
                                                const float* __restrict__ vb) {
    int z = blockIdx.z;
    const float* bias = z ? vb : ub;
    const __nv_bfloat16* xh = z ? g_ph : g_kh;
    const __nv_bfloat16* xl = z ? g_pl : g_kl;
    float* outg = z ? g_vp : g_uk;
    int ROWS = z ? L2P : SS;

    int gw = blockIdx.x * 8 + (threadIdx.x >> 5);
    int lane = threadIdx.x & 31;
    int ngroups = (ROWS + 7) >> 3;
    int jg = gw % ngroups;
    int rem = gw / ngroups;
    int h = rem & 7, b = rem >> 3;
    if (b >= BB) return;
    int jsub = lane >> 2, dq = lane & 3;
    int j = jg * 8 + jsub;
    float acc = 0.f;
    if (j < ROWS) {
        size_t base = ((size_t)(b * ROWS + j)) * DD + h * DH + dq * 16;
        uint4 h0 = *(const uint4*)&xh[base];
        uint4 h1 = *(const uint4*)&xh[base + 8];
        uint4 l0 = *(const uint4*)&xl[base];
        uint4 l1 = *(const uint4*)&xl[base + 8];
        uint32_t hs[8] = {h0.x,h0.y,h0.z,h0.w,h1.x,h1.y,h1.z,h1.w};
        uint32_t ls[8] = {l0.x,l0.y,l0.z,l0.w,l1.x,l1.y,l1.z,l1.w};
        const float* u = bias + h * DH + dq * 16;
        #pragma unroll
        for (int e = 0; e < 8; e++) {
            float2 f = unsplit(hs[e], ls[e]);
            acc += f.x * u[2*e] + f.y * u[2*e+1];
        }
    }
    acc += __shfl_xor_sync(0xffffffffu, acc, 1);
    acc += __shfl_xor_sync(0xffffffffu, acc, 2);
    if (dq == 0 && j < ROWS)
        outg[((size_t)(b * HH + h)) * ROWS + j] = acc;
}

// ---------------- GEMM (2-stage, validated R11 config) ----------------
#define G_AL  10240
#define G_BH  20480
#define G_BL  29184
#define G_STG 37888
#define G_SMEM (2*G_STG)

__global__ __launch_bounds__(256, 2) void gemm_proj_all() {
    extern __shared__ char smem[];
    uint32_t sb = (uint32_t)__cvta_generic_to_shared(smem);
    int tid = threadIdx.x, lane = tid & 31, wi = tid >> 5;
    int g = lane >> 2, t4 = lane & 3;
    int y = blockIdx.y;
    const __nv_bfloat16 *Ah, *Al, *Bh, *Bl;
    __nv_bfloat16 *Ch, *Cl;
    int M, row0;
    if (y < 192) {
        int sel = y >> 6;
        row0 = (y & 63) * 128; M = MROWS;
        if (sel == 0)      { Ah = g_xqh; Al = g_xql; Ch = g_qh; Cl = g_ql; }
        else if (sel == 1) { Ah = g_xkh; Al = g_xkl; Ch = g_kh; Cl = g_kl; }
        else               { Ah = g_xvh; Al = g_xvl; Ch = g_vh; Cl = g_vl; }
        Bh = g_wh + (size_t)sel * DD * DD;
        Bl = g_wl + (size_t)sel * DD * DD;
    } else {
        row0 = (y - 192) * 128; M = PROWS;
        Ah = g_xph; Al = g_xpl; Ch = g_ph; Cl = g_pl;
        Bh = g_wh + (size_t)3 * DD * DD;
        Bl = g_wl + (size_t)3 * DD * DD;
    }
    int col0 = blockIdx.x * 128;
    int wm = (wi & 3) * 32, wn = (wi >> 2) * 64;

    float acc[2][8][4];
    #pragma unroll
    for (int a = 0; a < 2; a++)
        #pragma unroll
        for (int b = 0; b < 8; b++)
            #pragma unroll
            for (int c = 0; c < 4; c++) acc[a][b][c] = 0.f;

    auto issue = [&](int it) {
        int k0 = it * 32;
        uint32_t st = sb + (it & 1) * G_STG;
        #pragma unroll
        for (int q = 0; q < 2; q++) {
            int c = q * 256 + tid;
            int m = c >> 2, seg = c & 3;
            bool ok = (row0 + m) < M;
            int mr = ok ? (row0 + m) : 0;
            cp16(st + m * 80 + seg * 16, Ah + (size_t)mr * DD + k0 + seg * 8, ok);
            cp16(st + G_AL + m * 80 + seg * 16, Al + (size_t)mr * DD + k0 + seg * 8, ok);
        }
        #pragma unroll
        for (int q = 0; q < 2; q++) {
            int c = q * 256 + tid;
            int k = c >> 4, seg = c & 15;
            cp16(st + G_BH + k * 272 + seg * 16, Bh + (size_t)(k0 + k) * DD + col0 + seg * 8, true);
            cp16(st + G_BL + k * 272 + seg * 16, Bl + (size_t)(k0 + k) * DD + col0 + seg * 8, true);
        }
        cpcommit();
    };

    issue(0);
    for (int it = 0; it < 16; it++) {
        if (it + 1 < 16) { issue(it + 1); cpwait<1>(); }
        else cpwait<0>();
        __syncthreads();
        uint32_t st = sb + (it & 1) * G_STG;
        #pragma unroll
        for (int kk = 0; kk < 32; kk += 16) {
            uint32_t ah[2][4], al[2][4];
            #pragma unroll
            for (int mi = 0; mi < 2; mi++) {
                uint32_t ad = st + (wm + 16 * mi + (lane & 15)) * 80 + (kk + ((lane >> 4) << 3)) * 2;
                ldsm4(ah[mi], ad);
                ldsm4(al[mi], ad + G_AL);
            }
            #pragma unroll
            for (int nh = 0; nh < 4; nh++) {
                int n0 = wn + 16 * nh;
                uint32_t bd = st + G_BH + (kk + (lane & 7) + (lane & 8)) * 272
                              + (n0 + ((lane & 16) >> 1)) * 2;
                uint32_t bh4[4], bl4[4];
                ldsm4t(bh4, bd);
                ldsm4t(bl4, bd + (G_BL - G_BH));
                #pragma unroll
                for (int half = 0; half < 2; half++) {
                    int nf = 2 * nh + half;
                    uint32_t bhh[2] = {bh4[2*half], bh4[2*half+1]};
                    uint32_t bll[2] = {bl4[2*half], bl4[2*half+1]};
                    #pragma unroll
                    for (int mi = 0; mi < 2; mi++)
                        mma3(acc[mi][nf], ah[mi], al[mi], bhh, bll);
                }
            }
        }
        __syncthreads();
    }

    #pragma unroll
    for (int mi = 0; mi < 2; mi++)
        #pragma unroll
        for (int nf = 0; nf < 8; nf++)
            #pragma unroll
            for (int half = 0; half < 2; half++) {
                int r = row0 + wm + 16 * mi + g + 8 * half;
                int c = col0 + wn + 8 * nf + 2 * t4;
                if (r < M) {
                    uint32_t h, l;
                    split_pair(acc[mi][nf][2*half], acc[mi][nf][2*half+1], h, l);
                    *(uint32_t*)&Ch[(size_t)r * DD + c] = h;
                    *(uint32_t*)&Cl[(size_t)r * DD + c] = l;
                }
            }
}

__global__ __launch_bounds__(256, 2) void gemm_out(float* __restrict__ Cf) {
    extern __shared__ char smem[];
    uint32_t sb = (uint32_t)__cvta_generic_to_shared(smem);
    int tid = threadIdx.x, lane = tid & 31, wi = tid >> 5;
    int g = lane >> 2, t4 = lane & 3;
    int row0 = blockIdx.y * 128, col0 = blockIdx.x * 128;
    int wm = (wi & 3) * 32, wn = (wi >> 2) * 64;
    const __nv_bfloat16* Ah = g_ch;
    const __nv_bfloat16* Al = g_cl;
    const __nv_bfloat16* Bh = g_wh + (size_t)4 * DD * DD;
    const __nv_bfloat16* Bl = g_wl + (size_t)4 * DD * DD;

    float acc[2][8][4];
    #pragma unroll
    for (int a = 0; a < 2; a++)
        #pragma unroll
        for (int b = 0; b < 8; b++)
            #pragma unroll
            for (int c = 0; c < 4; c++) acc[a][b][c] = 0.f;

    auto issue = [&](int it) {
        int k0 = it * 32;
        uint32_t st = sb + (it & 1) * G_STG;
        #pragma unroll
        for (int q = 0; q < 2; q++) {
            int c = q * 256 + tid;
            int m = c >> 2, seg = c & 3;
            cp16(st + m * 80 + seg * 16, Ah + (size_t)(row0 + m) * DD + k0 + seg * 8, true);
            cp16(st + G_AL + m * 80 + seg * 16, Al + (size_t)(row0 + m) * DD + k0 + seg * 8, true);
        }
        #pragma unroll
        for (int q = 0; q < 2; q++) {
            int c = q * 256 + tid;
            int k = c >> 4, seg = c & 15;
            cp16(st + G_BH + k * 272 + seg * 16, Bh + (size_t)(k0 + k) * DD + col0 + seg * 8, true);
            cp16(st + G_BL + k * 272 + seg * 16, Bl + (size_t)(k0 + k) * DD + col0 + seg * 8, true);
        }
        cpcommit();
    };

    issue(0);
    for (int it = 0; it < 16; it++) {
        if (it + 1 < 16) { issue(it + 1); cpwait<1>(); }
        else cpwait<0>();
        __syncthreads();
        uint32_t st = sb + (it & 1) * G_STG;
        #pragma unroll
        for (int kk = 0; kk < 32; kk += 16) {
            uint32_t ah[2][4], al[2][4];
            #pragma unroll
            for (int mi = 0; mi < 2; mi++) {
                uint32_t ad = st + (wm + 16 * mi + (lane & 15)) * 80 + (kk + ((lane >> 4) << 3)) * 2;
                ldsm4(ah[mi], ad);
                ldsm4(al[mi], ad + G_AL);
            }
            #pragma unroll
            for (int nh = 0; nh < 4; nh++) {
                int n0 = wn + 16 * nh;
                uint32_t bd = st + G_BH + (kk + (lane & 7) + (lane & 8)) * 272
                              + (n0 + ((lane & 16) >> 1)) * 2;
                uint32_t bh4[4], bl4[4];
                ldsm4t(bh4, bd);
                ldsm4t(bl4, bd + (G_BL - G_BH));
                #pragma unroll
                for (int half = 0; half < 2; half++) {
                    int nf = 2 * nh + half;
                    uint32_t bhh[2] = {bh4[2*half], bh4[2*half+1]};
                    uint32_t bll[2] = {bl4[2*half], bl4[2*half+1]};
                    #pragma unroll
                    for (int mi = 0; mi < 2; mi++)
                        mma3(acc[mi][nf], ah[mi], al[mi], bhh, bll);
                }
            }
        }
        __syncthreads();
    }

    #pragma unroll
    for (int mi = 0; mi < 2; mi++)
        #pragma unroll
        for (int nf = 0; nf < 8; nf++)
            #pragma unroll
            for (int half = 0; half < 2; half++) {
                int r = row0 + wm + 16 * mi + g + 8 * half;
                int c = col0 + wn + 8 * nf + 2 * t4;
                *(float2*)&Cf[(size_t)r * DD + c] =
                    make_float2(acc[mi][nf][2*half], acc[mi][nf][2*half+1]);
            }
}

// ---------------- fused flash attention v7: band-skipped pos GEMM ----------------
#define SQ_H  0
#define SQ_L  9216
#define SK_H  18432
#define SK_L  27648
#define SP_H  36864
#define SP_L  55296
#define SV_H  73728
#define SV_L  82944
#define SATT  92160
#define SATT_L (SATT + 9216)
#define SSTAT (SATT + 18432)
#define UKOFF (SSTAT + 768)
#define VPOFF (UKOFF + 512)
#define FL_SMEM (VPOFF + 1024)

__global__ __launch_bounds__(256, 2) void flash_v7() {
    extern __shared__ char smem[];
    uint32_t sb = (uint32_t)__cvta_generic_to_shared(smem);
    float* S32  = (float*)(smem + SATT);
    float* m_s  = (float*)(smem + SSTAT);
    float* l_s  = m_s + 64;
    float* al_s = m_s + 128;
    float* uk_s = (float*)(smem + UKOFF);
    float* vp_s = (float*)(smem + VPOFF);

    int tid = threadIdx.x, lane = tid & 31, wi = tid >> 5;
    int g = lane >> 2, t4 = lane & 3;
    int bh = blockIdx.y, b = bh >> 3, h = bh & 7;
    int i0 = blockIdx.x * 64;
    int wm = (wi & 1) * 32;       // 2 m-warps
    int wcol = wi >> 1;           // 4 n-warps

    // band-skip predicates for pos blocks: rows [rl0, rl0+16) need t in [48-rl0, 126-rl0]
    // block nh covers t in [wcol*32 + 16*nh, +16)
    bool needP[2][2];   // [nh][mi]
    #pragma unroll
    for (int nh = 0; nh < 2; nh++) {
        int t0 = wcol * 32 + 16 * nh;
        #pragma unroll
        for (int mi = 0; mi < 2; mi++) {
            int rl0 = wm + 16 * mi;
            needP[nh][mi] = (t0 + 16 > 48 - rl0) && (t0 <= 126 - rl0);
        }
    }

    float accO[2][2][4];
    #pragma unroll
    for (int a = 0; a < 2; a++)
        #pragma unroll
        for (int c = 0; c < 2; c++)
            #pragma unroll
            for (int e = 0; e < 4; e++) accO[a][c][e] = 0.f;

    auto issue_kp = [&](int jt) {
        int j0 = jt * 64;
        int pbase = 960 + j0 - i0;
        #pragma unroll
        for (int q = 0; q < 2; q++) {
            int c = q * 256 + tid;
            int row = c >> 3, seg = c & 7;
            size_t src = (size_t)(b * SS + j0 + row) * DD + h * DH + seg * 8;
            uint32_t d = sb + row * 144 + seg * 16;
            cp16(d + SK_H, g_kh + src, true);
            cp16(d + SK_L, g_kl + src, true);
        }
        #pragma unroll
        for (int q = 0; q < 4; q++) {
            int c = q * 256 + tid;
            int row = c >> 3, seg = c & 7;
            bool ok = row < 127;
            int rc = ok ? row : 0;
            size_t src = (size_t)(b * L2P + pbase + rc) * DD + h * DH + seg * 8;
            uint32_t d = sb + row * 144 + seg * 16;
            cp16(d + SP_H, g_ph + src, ok);
            cp16(d + SP_L, g_pl + src, ok);
        }
        if (tid < 16)
            cp16(sb + UKOFF + (jt & 1) * 256 + tid * 16,
                 g_uk + ((size_t)(b * HH + h)) * SS + j0 + tid * 4, true);
        if (tid < 128)
            cp4(sb + VPOFF + (jt & 1) * 512 + tid * 4,
                g_vp + ((size_t)(b * HH + h)) * L2P + pbase + tid);
        cpcommit();
    };
    auto issue_v = [&](int jt) {
        int j0 = jt * 64;
        #pragma unroll
        for (int q = 0; q < 2; q++) {
            int c = q * 256 + tid;
            int row = c >> 3, seg = c & 7;
            size_t src = (size_t)(b * SS + j0 + row) * DD + h * DH + seg * 8;
            uint32_t d = sb + row * 144 + seg * 16;
            cp16(d + SV_H, g_vh + src, true);
            cp16(d + SV_L, g_vl + src, true);
        }
        cpcommit();
    };

    #pragma unroll
    for (int q = 0; q < 2; q++) {
        int c = q * 256 + tid;
        int row = c >> 3, seg = c & 7;
        size_t src = (size_t)(b * SS + i0 + row) * DD + h * DH + seg * 8;
        uint32_t d = sb + row * 144 + seg * 16;
        cp16(d + SQ_H, g_qh + src, true);
        cp16(d + SQ_L, g_ql + src, true);
    }
    issue_kp(0);
    issue_v(0);

    for (int jt = 0; jt < 16; jt++) {
        cpwait<1>();
        __syncthreads();
        int ub2 = (jt & 1) * 64;
        int vb2 = (jt & 1) * 128;

        float accC[2][2][4];
        float accR[2][4][4];
        #pragma unroll
        for (int a = 0; a < 2; a++) {
            #pragma unroll
            for (int c = 0; c < 2; c++)
                #pragma unroll
                for (int e = 0; e < 4; e++) accC[a][c][e] = 0.f;
            #pragma unroll
            for (int c = 0; c < 4; c++)
                #pragma unroll
                for (int e = 0; e < 4; e++) accR[a][c][e] = 0.f;
        }

        #pragma unroll
        for (int kk = 0; kk < 64; kk += 16) {
            uint32_t ah[2][4], al[2][4];
            #pragma unroll
            for (int mi = 0; mi < 2; mi++) {
                uint32_t ad = sb + SQ_H + (wm + 16 * mi + (lane & 15)) * 144
                              + (kk + ((lane >> 4) << 3)) * 2;
                ldsm4(ah[mi], ad);
                ldsm4(al[mi], ad + (SQ_L - SQ_H));
            }
            { // content: 16 cols
                int n0 = wcol * 16;
                uint32_t bd = sb + SK_H + (n0 + (lane & 15)) * 144 + (kk + ((lane >> 4) << 3)) * 2;
                uint32_t bh4[4], bl4[4];
                ldsm4(bh4, bd);
                ldsm4(bl4, bd + (SK_L - SK_H));
                #pragma unroll
                for (int half = 0; half < 2; half++) {
                    uint32_t bhh[2] = {bh4[half], bh4[half+2]};
                    uint32_t bll[2] = {bl4[half], bl4[half+2]};
                    #pragma unroll
                    for (int mi = 0; mi < 2; mi++)
                        mma3(accC[mi][half], ah[mi], al[mi], bhh, bll);
                }
            }
            #pragma unroll
            for (int nh = 0; nh < 2; nh++) { // pos: 32 cols, band-skipped
                if (needP[nh][0] || needP[nh][1]) {
                    int n0 = wcol * 32 + 16 * nh;
                    uint32_t bd = sb + SP_H + (n0 + (lane & 15)) * 144 + (kk + ((lane >> 4) << 3)) * 2;
                    uint32_t bh4[4], bl4[4];
                    ldsm4(bh4, bd);
                    ldsm4(bl4, bd + (SP_L - SP_H));
                    #pragma unroll
                    for (int half = 0; half < 2; half++) {
                        int nf = 2 * nh + half;
                        uint32_t bhh[2] = {bh4[half], bh4[half+2]};
                        uint32_t bll[2] = {bl4[half], bl4[half+2]};
                        #pragma unroll
                        for (int mi = 0; mi < 2; mi++)
                            if (needP[nh][mi])
                                mma3(accR[mi][nf], ah[mi], al[mi], bhh, bll);
                    }
                }
            }
        }
        // dump content + uk (exclusive cells)
        #pragma unroll
        for (int mi = 0; mi < 2; mi++)
            #pragma unroll
            for (int nf = 0; nf < 2; nf++) {
                int jj = wcol * 16 + 8 * nf + 2 * t4;
                int rl = wm + 16 * mi + g;
                S32[rl * 68 + jj]     = (accC[mi][nf][0] + uk_s[ub2 + jj])     * SCALE;
                S32[rl * 68 + jj + 1] = (accC[mi][nf][1] + uk_s[ub2 + jj + 1]) * SCALE;
                S32[(rl + 8) * 68 + jj]     = (accC[mi][nf][2] + uk_s[ub2 + jj])     * SCALE;
                S32[(rl + 8) * 68 + jj + 1] = (accC[mi][nf][3] + uk_s[ub2 + jj + 1]) * SCALE;
            }
        __syncthreads();
        if (jt < 15) issue_kp(jt + 1); else cpcommit();

        // scatter pos: jl = t + rl - 63 (injective per row); band-skipped blocks never store
        #pragma unroll
        for (int mi = 0; mi < 2; mi++)
            #pragma unroll
            for (int nf = 0; nf < 4; nf++) {
                if (!needP[nf >> 1][mi]) continue;
                int t = wcol * 32 + 8 * nf + 2 * t4;
                #pragma unroll
                for (int half = 0; half < 2; half++) {
                    int rl = wm + 16 * mi + g + 8 * half;
                    int jl = t + rl - 63;
                    if (jl >= 0 && jl < 64)
                        S32[rl * 68 + jl] += (accR[mi][nf][2*half] + vp_s[vb2 + t]) * SCALE;
                    int jl2 = jl + 1;
                    if (jl2 >= 0 && jl2 < 64)
                        S32[rl * 68 + jl2] += (accR[mi][nf][2*half+1] + vp_s[vb2 + t + 1]) * SCALE;
                }
            }
        __syncthreads();

        // ---- online softmax (4 threads per row, 16 cols each) ----
        int r = tid >> 2, q4 = tid & 3;
        float p[16];
        {
            const float4* Sp = (const float4*)(S32 + r * 68 + q4 * 16);
            float tm = -1e30f;
            #pragma unroll
            for (int q = 0; q < 4; q++) {
                float4 v = Sp[q];
                p[4*q] = v.x; p[4*q+1] = v.y; p[4*q+2] = v.z; p[4*q+3] = v.w;
                tm = fmaxf(tm, fmaxf(fmaxf(v.x, v.y), fmaxf(v.z, v.w)));
            }
            tm = fmaxf(tm, __shfl_xor_sync(0xffffffffu, tm, 1));
            tm = fmaxf(tm, __shfl_xor_sync(0xffffffffu, tm, 2));
            float mo = jt ? m_s[r] : -1e30f;
            float lo = jt ? l_s[r] : 0.f;
            float mn = fmaxf(mo, tm);
            float alpha = __expf(mo - mn);
            float sum = 0.f;
            #pragma unroll
            for (int c = 0; c < 16; c++) { p[c] = __expf(p[c] - mn); sum += p[c]; }
            sum += __shfl_xor_sync(0xffffffffu, sum, 1);
            sum += __shfl_xor_sync(0xffffffffu, sum, 2);
            if (q4 == 0) { m_s[r] = mn; l_s[r] = alpha * lo + sum; al_s[r] = alpha; }
        }
        __syncthreads();

        // write probs (split bf16) into attn buffer (aliases S32)
        {
            uint32_t* ahp = (uint32_t*)(smem + SATT)   + r * 36 + q4 * 8;
            uint32_t* alp = (uint32_t*)(smem + SATT_L) + r * 36 + q4 * 8;
            #pragma unroll
            for (int q = 0; q < 8; q++) {
                uint32_t hh, ll;
                split_pair(p[2*q], p[2*q+1], hh, ll);
                ahp[q] = hh; alp[q] = ll;
            }
        }
        cpwait<1>();              // V(jt) ready
        __syncthreads();

        // rescale O, then accumulate P @ V
        #pragma unroll
        for (int mi = 0; mi < 2; mi++) {
            float a1 = al_s[wm + 16 * mi + g];
            float a2 = al_s[wm + 16 * mi + g + 8];
            #pragma unroll
            for (int nf = 0; nf < 2; nf++) {
                accO[mi][nf][0] *= a1; accO[mi][nf][1] *= a1;
                accO[mi][nf][2] *= a2; accO[mi][nf][3] *= a2;
            }
        }
        #pragma unroll
        for (int kk = 0; kk < 64; kk += 16) {
            uint32_t ah[2][4], al[2][4];
            #pragma unroll
            for (int mi = 0; mi < 2; mi++) {
                uint32_t ad = sb + SATT + (wm + 16 * mi + (lane & 15)) * 144
                              + (kk + ((lane >> 4) << 3)) * 2;
                ldsm4(ah[mi], ad);
                ldsm4(al[mi], ad + (SATT_L - SATT));
            }
            int n0 = wcol * 16;
            uint32_t bd = sb + SV_H + (kk + (lane & 7) + (lane & 8)) * 144
                          + (n0 + ((lane & 16) >> 1)) * 2;
            uint32_t bh4[4], bl4[4];
            ldsm4t(bh4, bd);
            ldsm4t(bl4, bd + (SV_L - SV_H));
            #pragma unroll
            for (int half = 0; half < 2; half++) {
                uint32_t bhh[2] = {bh4[2*half], bh4[2*half+1]};
                uint32_t bll[2] = {bl4[2*half], bl4[2*half+1]};
                #pragma unroll
                for (int mi = 0; mi < 2; mi++)
                    mma3(accO[mi][half], ah[mi], al[mi], bhh, bll);
            }
        }
        __syncthreads();
        if (jt < 15) issue_v(jt + 1); else cpcommit();
    }

    // epilogue: normalize, split, store context
    #pragma unroll
    for (int mi = 0; mi < 2; mi++)
        #pragma unroll
        for (int nf = 0; nf < 2; nf++)
            #pragma unroll
            for (int half = 0; half < 2; half++) {
                int rl = wm + 16 * mi + g + 8 * half;
                float inv = 1.f / l_s[rl];
                int dl = wcol * 16 + 8 * nf + 2 * t4;
                uint32_t hh, ll;
                split_pair(accO[mi][nf][2*half] * inv, accO[mi][nf][2*half+1] * inv, hh, ll);
                size_t o = (size_t)(b * SS + i0 + rl) * DD + h * DH + dl;
                *(uint32_t*)&g_ch[o] = hh;
                *(uint32_t*)&g_cl[o] = ll;
            }
}

// ---------------- launch ----------------
extern "C" void kernel_launch(void* const* d_in, const int* in_sizes, int n_in,
                              void* d_out, int out_size) {
    const float* query = (const float*)d_in[0];
    const float* key   = (const float*)d_in[1];
    const float* value = (const float*)d_in[2];
    const float* pos   = (const float*)d_in[3];
    const float* Wq    = (const float*)d_in[4];
    const float* Wk    = (const float*)d_in[5];
    const float* Wv    = (const float*)d_in[6];
    const float* Wp    = (const float*)d_in[7];
    const float* ub    = (const float*)d_in[8];
    const float* vb    = (const float*)d_in[9];
    const float* Wo    = (const float*)d_in[10];
    float* out = (float*)d_out;

    static bool attr_done = false;
    if (!attr_done) {
        cudaFuncSetAttribute(gemm_proj_all, cudaFuncAttributeMaxDynamicSharedMemorySize, G_SMEM);
        cudaFuncSetAttribute(gemm_out,      cudaFuncAttributeMaxDynamicSharedMemorySize, G_SMEM);
        cudaFuncSetAttribute(flash_v7,      cudaFuncAttributeMaxDynamicSharedMemorySize, FL_SMEM);
        attr_done = true;
    }

    dim3 blk(256);

    split_all<<<(C_W + 255)/256, blk>>>((const float4*)query, (const float4*)key,
                                        (const float4*)value, (const float4*)pos,
                                        (const float4*)Wq, (const float4*)Wk,
                                        (const float4*)Wv, (const float4*)Wp,
                                        (const float4*)Wo);

    gemm_proj_all<<<dim3(4, 320), blk, G_SMEM>>>();

    biasdot2<<<dim3((8*8*((L2P+7)/8) + 7)/8, 1, 2), blk>>>(ub, vb);

    flash_v7<<<dim3(SS/64, BB*HH), blk, FL_SMEM>>>();

    gemm_out<<<dim3(4, 64), blk, G_SMEM>>>(out);
}

// round 16
// speedup vs baseline: 1.0331x; 1.0331x over previous
#include <cuda_runtime.h>
#include <cuda_bf16.h>
#include <cstdint>

#define BB 8
#define SS 1024
#define DD 512
#define HH 8
#define DH 64
#define L2P 2047
#define SCALE 0.125f
#define MROWS (BB*SS)      // 8192
#define PROWS (BB*L2P)     // 16376

// ---------------- scratch ----------------
__device__ __nv_bfloat16 g_xqh[MROWS*DD], g_xql[MROWS*DD];
__device__ __nv_bfloat16 g_xkh[MROWS*DD], g_xkl[MROWS*DD];
__device__ __nv_bfloat16 g_xvh[MROWS*DD], g_xvl[MROWS*DD];
__device__ __nv_bfloat16 g_xph[PROWS*DD], g_xpl[PROWS*DD];
__device__ __nv_bfloat16 g_wh[5*DD*DD], g_wl[5*DD*DD];
__device__ __nv_bfloat16 g_qh[MROWS*DD],  g_ql[MROWS*DD];
__device__ __nv_bfloat16 g_kh[MROWS*DD],  g_kl[MROWS*DD];
__device__ __nv_bfloat16 g_vh[MROWS*DD],  g_vl[MROWS*DD];
__device__ __nv_bfloat16 g_ph[(PROWS+8)*DD], g_pl[(PROWS+8)*DD];
__device__ __nv_bfloat16 g_ch[MROWS*DD], g_cl[MROWS*DD];
__device__ float g_uk[BB*HH*SS];
__device__ float g_vp[BB*HH*L2P + 64];

// ---------------- helpers ----------------
__device__ __forceinline__ void split_pair(float x0, float x1, uint32_t& h, uint32_t& l) {
    __nv_bfloat162 hh = __floats2bfloat162_rn(x0, x1);
    float r0 = x0 - __bfloat162float(hh.x);
    float r1 = x1 - __bfloat162float(hh.y);
    __nv_bfloat162 ll = __floats2bfloat162_rn(r0, r1);
    h = *reinterpret_cast<uint32_t*>(&hh);
    l = *reinterpret_cast<uint32_t*>(&ll);
}
__device__ __forceinline__ float2 unsplit(uint32_t h, uint32_t l) {
    __nv_bfloat162 hh = *reinterpret_cast<__nv_bfloat162*>(&h);
    __nv_bfloat162 ll = *reinterpret_cast<__nv_bfloat162*>(&l);
    return make_float2(__bfloat162float(hh.x) + __bfloat162float(ll.x),
                       __bfloat162float(hh.y) + __bfloat162float(ll.y));
}
__device__ __forceinline__ void mma16816(float d[4], const uint32_t a[4], const uint32_t b[2]) {
    asm volatile(
        "mma.sync.aligned.m16n8k16.row.col.f32.bf16.bf16.f32 "
        "{%0,%1,%2,%3}, {%4,%5,%6,%7}, {%8,%9}, {%0,%1,%2,%3};\n"
        : "+f"(d[0]), "+f"(d[1]), "+f"(d[2]), "+f"(d[3])
        : "r"(a[0]), "r"(a[1]), "r"(a[2]), "r"(a[3]), "r"(b[0]), "r"(b[1]));
}
__device__ __forceinline__ void mma3(float d[4], const uint32_t ah[4], const uint32_t al[4],
                                     const uint32_t bh[2], const uint32_t bl[2]) {
    mma16816(d, ah, bh);
    mma16816(d, ah, bl);
    mma16816(d, al, bh);
}
__device__ __forceinline__ void ldsm4(uint32_t r[4], uint32_t addr) {
    asm volatile("ldmatrix.sync.aligned.m8n8.x4.shared.b16 {%0,%1,%2,%3},[%4];"
        : "=r"(r[0]), "=r"(r[1]), "=r"(r[2]), "=r"(r[3]) : "r"(addr));
}
__device__ __forceinline__ void ldsm4t(uint32_t r[4], uint32_t addr) {
    asm volatile("ldmatrix.sync.aligned.m8n8.x4.trans.shared.b16 {%0,%1,%2,%3},[%4];"
        : "=r"(r[0]), "=r"(r[1]), "=r"(r[2]), "=r"(r[3]) : "r"(addr));
}
__device__ __forceinline__ void cp16(uint32_t dst, const void* src, bool pred) {
    int sz = pred ? 16 : 0;
    asm volatile("cp.async.cg.shared.global [%0],[%1],16,%2;\n"
        :: "r"(dst), "l"(src), "r"(sz));
}
__device__ __forceinline__ void cp4(uint32_t dst, const void* src) {
    asm volatile("cp.async.ca.shared.global [%0],[%1],4;\n" :: "r"(dst), "l"(src));
}
__device__ __forceinline__ void cpcommit() { asm volatile("cp.async.commit_group;\n"); }
template<int N> __device__ __forceinline__ void cpwait() {
    asm volatile("cp.async.wait_group %0;\n" :: "n"(N));
}
__device__ __forceinline__ void barsync(int id) {
    asm volatile("bar.sync %0, 128;" :: "r"(id) : "memory");
}

// ---------------- merged split prepass ----------------
#define C_Q  (MROWS*DD/4)
#define C_K  (2*C_Q)
#define C_V  (3*C_Q)
#define C_P  (C_V + PROWS*DD/4)
#define C_W  (C_P + 5*(DD*DD/4))
__global__ __launch_bounds__(256) void split_all(const float4* __restrict__ q,
                                                 const float4* __restrict__ k,
                                                 const float4* __restrict__ v,
                                                 const float4* __restrict__ p,
                                                 const float4* __restrict__ W0,
                                                 const float4* __restrict__ W1,
                                                 const float4* __restrict__ W2,
                                                 const float4* __restrict__ W3,
                                                 const float4* __restrict__ W4) {
    long i = (long)blockIdx.x * 256 + threadIdx.x;
    const float4* src; uint32_t *hi, *lo; long off;
    if (i < C_Q)      { src = q; hi = (uint32_t*)g_xqh; lo = (uint32_t*)g_xql; off = i; }
    else if (i < C_K) { src = k; hi = (uint32_t*)g_xkh; lo = (uint32_t*)g_xkl; off = i - C_Q; }
    else if (i < C_V) { src = v; hi = (uint32_t*)g_xvh; lo = (uint32_t*)g_xvl; off = i - C_K; }
    else if (i < C_P) { src = p; hi = (uint32_t*)g_xph; lo = (uint32_t*)g_xpl; off = i - C_V; }
    else if (i < C_W) {
        long wi = i - C_P;
        int z = (int)(wi / (DD*DD/4));
        off = wi - (long)z * (DD*DD/4);
        src = (z == 0) ? W0 : (z == 1) ? W1 : (z == 2) ? W2 : (z == 3) ? W3 : W4;
        hi = (uint32_t*)g_wh + (size_t)z * (DD*DD/2);
        lo = (uint32_t*)g_wl + (size_t)z * (DD*DD/2);
    } else return;
    float4 val = src[off];
    uint32_t h0, l0, h1, l1;
    split_pair(val.x, val.y, h0, l0);
    split_pair(val.z, val.w, h1, l1);
    hi[2*off] = h0; hi[2*off+1] = h1;
    lo[2*off] = l0; lo[2*off+1] = l1;
}

// ---------------- merged bias GEMV ----------------
__global__ __launch_bounds__(256) void biasdot2(const float* __restrict__ ub,
                                                const float* __restrict__ vb) {
    int z = blockIdx.z;
    const float* bias = z ? vb : ub;
    const __nv_bfloat16* xh = z ? g_ph : g_kh;
    const __nv_bfloat16* xl = z ? g_pl : g_kl;
    float* outg = z ? g_vp : g_uk;
    int ROWS = z ? L2P : SS;

    int gw = blockIdx.x * 8 + (threadIdx.x >> 5);
    int lane = threadIdx.x & 31;
    int ngroups = (ROWS + 7) >> 3;
    int jg = gw % ngroups;
    int rem = gw / ngroups;
    int h = rem & 7, b = rem >> 3;
    if (b >= BB) return;
    int jsub = lane >> 2, dq = lane & 3;
    int j = jg * 8 + jsub;
    float acc = 0.f;
    if (j < ROWS) {
        size_t base = ((size_t)(b * ROWS + j)) * DD + h * DH + dq * 16;
        uint4 h0 = *(const uint4*)&xh[base];
        uint4 h1 = *(const uint4*)&xh[base + 8];
        uint4 l0 = *(const uint4*)&xl[base];
        uint4 l1 = *(const uint4*)&xl[base + 8];
        uint32_t hs[8] = {h0.x,h0.y,h0.z,h0.w,h1.x,h1.y,h1.z,h1.w};
        uint32_t ls[8] = {l0.x,l0.y,l0.z,l0.w,l1.x,l1.y,l1.z,l1.w};
        const float* u = bias + h * DH + dq * 16;
        #pragma unroll
        for (int e = 0; e < 8; e++) {
            float2 f = unsplit(hs[e], ls[e]);
            acc += f.x * u[2*e] + f.y * u[2*e+1];
        }
    }
    acc += __shfl_xor_sync(0xffffffffu, acc, 1);
    acc += __shfl_xor_sync(0xffffffffu, acc, 2);
    if (dq == 0 && j < ROWS)
        outg[((size_t)(b * HH + h)) * ROWS + j] = acc;
}

// ---------------- GEMM (2-stage, validated R11 config) ----------------
#define G_AL  10240
#define G_BH  20480
#define G_BL  29184
#define G_STG 37888
#define G_SMEM (2*G_STG)

__global__ __launch_bounds__(256, 2) void gemm_proj_all() {
    extern __shared__ char smem[];
    uint32_t sb = (uint32_t)__cvta_generic_to_shared(smem);
    int tid = threadIdx.x, lane = tid & 31, wi = tid >> 5;
    int g = lane >> 2, t4 = lane & 3;
    int y = blockIdx.y;
    const __nv_bfloat16 *Ah, *Al, *Bh, *Bl;
    __nv_bfloat16 *Ch, *Cl;
    int M, row0;
    if (y < 192) {
        int sel = y >> 6;
        row0 = (y & 63) * 128; M = MROWS;
        if (sel == 0)      { Ah = g_xqh; Al = g_xql; Ch = g_qh; Cl = g_ql; }
        else if (sel == 1) { Ah = g_xkh; Al = g_xkl; Ch = g_kh; Cl = g_kl; }
        else               { Ah = g_xvh; Al = g_xvl; Ch = g_vh; Cl = g_vl; }
        Bh = g_wh + (size_t)sel * DD * DD;
        Bl = g_wl + (size_t)sel * DD * DD;
    } else {
        row0 = (y - 192) * 128; M = PROWS;
        Ah = g_xph; Al = g_xpl; Ch = g_ph; Cl = g_pl;
        Bh = g_wh + (size_t)3 * DD * DD;
        Bl = g_wl + (size_t)3 * DD * DD;
    }
    int col0 = blockIdx.x * 128;
    int wm = (wi & 3) * 32, wn = (wi >> 2) * 64;

    float acc[2][8][4];
    #pragma unroll
    for (int a = 0; a < 2; a++)
        #pragma unroll
        for (int b = 0; b < 8; b++)
            #pragma unroll
            for (int c = 0; c < 4; c++) acc[a][b][c] = 0.f;

    auto issue = [&](int it) {
        int k0 = it * 32;
        uint32_t st = sb + (it & 1) * G_STG;
        #pragma unroll
        for (int q = 0; q < 2; q++) {
            int c = q * 256 + tid;
            int m = c >> 2, seg = c & 3;
            bool ok = (row0 + m) < M;
            int mr = ok ? (row0 + m) : 0;
            cp16(st + m * 80 + seg * 16, Ah + (size_t)mr * DD + k0 + seg * 8, ok);
            cp16(st + G_AL + m * 80 + seg * 16, Al + (size_t)mr * DD + k0 + seg * 8, ok);
        }
        #pragma unroll
        for (int q = 0; q < 2; q++) {
            int c = q * 256 + tid;
            int k = c >> 4, seg = c & 15;
            cp16(st + G_BH + k * 272 + seg * 16, Bh + (size_t)(k0 + k) * DD + col0 + seg * 8, true);
            cp16(st + G_BL + k * 272 + seg * 16, Bl + (size_t)(k0 + k) * DD + col0 + seg * 8, true);
        }
        cpcommit();
    };

    issue(0);
    for (int it = 0; it < 16; it++) {
        if (it + 1 < 16) { issue(it + 1); cpwait<1>(); }
        else cpwait<0>();
        __syncthreads();
        uint32_t st = sb + (it & 1) * G_STG;
        #pragma unroll
        for (int kk = 0; kk < 32; kk += 16) {
            uint32_t ah[2][4], al[2][4];
            #pragma unroll
            for (int mi = 0; mi < 2; mi++) {
                uint32_t ad = st + (wm + 16 * mi + (lane & 15)) * 80 + (kk + ((lane >> 4) << 3)) * 2;
                ldsm4(ah[mi], ad);
                ldsm4(al[mi], ad + G_AL);
            }
            #pragma unroll
            for (int nh = 0; nh < 4; nh++) {
                int n0 = wn + 16 * nh;
                uint32_t bd = st + G_BH + (kk + (lane & 7) + (lane & 8)) * 272
                              + (n0 + ((lane & 16) >> 1)) * 2;
                uint32_t bh4[4], bl4[4];
                ldsm4t(bh4, bd);
                ldsm4t(bl4, bd + (G_BL - G_BH));
                #pragma unroll
                for (int half = 0; half < 2; half++) {
                    int nf = 2 * nh + half;
                    uint32_t bhh[2] = {bh4[2*half], bh4[2*half+1]};
                    uint32_t bll[2] = {bl4[2*half], bl4[2*half+1]};
                    #pragma unroll
                    for (int mi = 0; mi < 2; mi++)
                        mma3(acc[mi][nf], ah[mi], al[mi], bhh, bll);
                }
            }
        }
        __syncthreads();
    }

    #pragma unroll
    for (int mi = 0; mi < 2; mi++)
        #pragma unroll
        for (int nf = 0; nf < 8; nf++)
            #pragma unroll
            for (int half = 0; half < 2; half++) {
                int r = row0 + wm + 16 * mi + g + 8 * half;
                int c = col0 + wn + 8 * nf + 2 * t4;
                if (r < M) {
                    uint32_t h, l;
                    split_pair(acc[mi][nf][2*half], acc[mi][nf][2*half+1], h, l);
                    *(uint32_t*)&Ch[(size_t)r * DD + c] = h;
                    *(uint32_t*)&Cl[(size_t)r * DD + c] = l;
                }
            }
}

__global__ __launch_bounds__(256, 2) void gemm_out(float* __restrict__ Cf) {
    extern __shared__ char smem[];
    uint32_t sb = (uint32_t)__cvta_generic_to_shared(smem);
    int tid = threadIdx.x, lane = tid & 31, wi = tid >> 5;
    int g = lane >> 2, t4 = lane & 3;
    int row0 = blockIdx.y * 128, col0 = blockIdx.x * 128;
    int wm = (wi & 3) * 32, wn = (wi >> 2) * 64;
    const __nv_bfloat16* Ah = g_ch;
    const __nv_bfloat16* Al = g_cl;
    const __nv_bfloat16* Bh = g_wh + (size_t)4 * DD * DD;
    const __nv_bfloat16* Bl = g_wl + (size_t)4 * DD * DD;

    float acc[2][8][4];
    #pragma unroll
    for (int a = 0; a < 2; a++)
        #pragma unroll
        for (int b = 0; b < 8; b++)
            #pragma unroll
            for (int c = 0; c < 4; c++) acc[a][b][c] = 0.f;

    auto issue = [&](int it) {
        int k0 = it * 32;
        uint32_t st = sb + (it & 1) * G_STG;
        #pragma unroll
        for (int q = 0; q < 2; q++) {
            int c = q * 256 + tid;
            int m = c >> 2, seg = c & 3;
            cp16(st + m * 80 + seg * 16, Ah + (size_t)(row0 + m) * DD + k0 + seg * 8, true);
            cp16(st + G_AL + m * 80 + seg * 16, Al + (size_t)(row0 + m) * DD + k0 + seg * 8, true);
        }
        #pragma unroll
        for (int q = 0; q < 2; q++) {
            int c = q * 256 + tid;
            int k = c >> 4, seg = c & 15;
            cp16(st + G_BH + k * 272 + seg * 16, Bh + (size_t)(k0 + k) * DD + col0 + seg * 8, true);
            cp16(st + G_BL + k * 272 + seg * 16, Bl + (size_t)(k0 + k) * DD + col0 + seg * 8, true);
        }
        cpcommit();
    };

    issue(0);
    for (int it = 0; it < 16; it++) {
        if (it + 1 < 16) { issue(it + 1); cpwait<1>(); }
        else cpwait<0>();
        __syncthreads();
        uint32_t st = sb + (it & 1) * G_STG;
        #pragma unroll
        for (int kk = 0; kk < 32; kk += 16) {
            uint32_t ah[2][4], al[2][4];
            #pragma unroll
            for (int mi = 0; mi < 2; mi++) {
                uint32_t ad = st + (wm + 16 * mi + (lane & 15)) * 80 + (kk + ((lane >> 4) << 3)) * 2;
                ldsm4(ah[mi], ad);
                ldsm4(al[mi], ad + G_AL);
            }
            #pragma unroll
            for (int nh = 0; nh < 4; nh++) {
                int n0 = wn + 16 * nh;
                uint32_t bd = st + G_BH + (kk + (lane & 7) + (lane & 8)) * 272
                              + (n0 + ((lane & 16) >> 1)) * 2;
                uint32_t bh4[4], bl4[4];
                ldsm4t(bh4, bd);
                ldsm4t(bl4, bd + (G_BL - G_BH));
                #pragma unroll
                for (int half = 0; half < 2; half++) {
                    int nf = 2 * nh + half;
                    uint32_t bhh[2] = {bh4[2*half], bh4[2*half+1]};
                    uint32_t bll[2] = {bl4[2*half], bl4[2*half+1]};
                    #pragma unroll
                    for (int mi = 0; mi < 2; mi++)
                        mma3(acc[mi][nf], ah[mi], al[mi], bhh, bll);
                }
            }
        }
        __syncthreads();
    }

    #pragma unroll
    for (int mi = 0; mi < 2; mi++)
        #pragma unroll
        for (int nf = 0; nf < 8; nf++)
            #pragma unroll
            for (int half = 0; half < 2; half++) {
                int r = row0 + wm + 16 * mi + g + 8 * half;
                int c = col0 + wn + 8 * nf + 2 * t4;
                *(float2*)&Cf[(size_t)r * DD + c] =
                    make_float2(acc[mi][nf][2*half], acc[mi][nf][2*half+1]);
            }
}

// ---------------- fused flash attention v8: group-local barriers ----------------
// warps: wm = (wi>>2)*32 (group = tid/128), wcol = wi&3
// attn aliasing: hi at byte r*272, lo at r*272+144 (row-local clobber only)
#define SQ_H  0
#define SQ_L  9216
#define SK_H  18432
#define SK_L  27648
#define SP_H  36864
#define SP_L  55296
#define SV_H  73728
#define SV_L  82944
#define SATT  92160
#define SSTAT (SATT + 17408)
#define UKOFF (SSTAT + 768)
#define VPOFF (UKOFF + 512)
#define FL_SMEM (VPOFF + 1024)

__global__ __launch_bounds__(256, 2) void flash_v8() {
    extern __shared__ char smem[];
    uint32_t sb = (uint32_t)__cvta_generic_to_shared(smem);
    float* S32  = (float*)(smem + SATT);
    float* m_s  = (float*)(smem + SSTAT);
    float* l_s  = m_s + 64;
    float* al_s = m_s + 128;
    float* uk_s = (float*)(smem + UKOFF);
    float* vp_s = (float*)(smem + VPOFF);

    int tid = threadIdx.x, lane = tid & 31, wi = tid >> 5;
    int g = lane >> 2, t4 = lane & 3;
    int bh = blockIdx.y, b = bh >> 3, h = bh & 7;
    int i0 = blockIdx.x * 64;
    int wm = (wi >> 2) * 32;      // group-contiguous m ownership
    int wcol = wi & 3;
    int gid = (wi >> 2) + 1;      // named barrier id 1/2

    float accO[2][2][4];
    #pragma unroll
    for (int a = 0; a < 2; a++)
        #pragma unroll
        for (int c = 0; c < 2; c++)
            #pragma unroll
            for (int e = 0; e < 4; e++) accO[a][c][e] = 0.f;

    auto issue_kp = [&](int jt) {
        int j0 = jt * 64;
        int pbase = 960 + j0 - i0;
        #pragma unroll
        for (int q = 0; q < 2; q++) {
            int c = q * 256 + tid;
            int row = c >> 3, seg = c & 7;
            size_t src = (size_t)(b * SS + j0 + row) * DD + h * DH + seg * 8;
            uint32_t d = sb + row * 144 + seg * 16;
            cp16(d + SK_H, g_kh + src, true);
            cp16(d + SK_L, g_kl + src, true);
        }
        #pragma unroll
        for (int q = 0; q < 4; q++) {
            int c = q * 256 + tid;
            int row = c >> 3, seg = c & 7;
            bool ok = row < 127;
            int rc = ok ? row : 0;
            size_t src = (size_t)(b * L2P + pbase + rc) * DD + h * DH + seg * 8;
            uint32_t d = sb + row * 144 + seg * 16;
            cp16(d + SP_H, g_ph + src, ok);
            cp16(d + SP_L, g_pl + src, ok);
        }
        if (tid < 16)
            cp16(sb + UKOFF + (jt & 1) * 256 + tid * 16,
                 g_uk + ((size_t)(b * HH + h)) * SS + j0 + tid * 4, true);
        if (tid < 128)
            cp4(sb + VPOFF + (jt & 1) * 512 + tid * 4,
                g_vp + ((size_t)(b * HH + h)) * L2P + pbase + tid);
        cpcommit();
    };
    auto issue_v = [&](int jt) {
        int j0 = jt * 64;
        #pragma unroll
        for (int q = 0; q < 2; q++) {
            int c = q * 256 + tid;
            int row = c >> 3, seg = c & 7;
            size_t src = (size_t)(b * SS + j0 + row) * DD + h * DH + seg * 8;
            uint32_t d = sb + row * 144 + seg * 16;
            cp16(d + SV_H, g_vh + src, true);
            cp16(d + SV_L, g_vl + src, true);
        }
        cpcommit();
    };

    // prologue: Q + KP(0) in one group
    #pragma unroll
    for (int q = 0; q < 2; q++) {
        int c = q * 256 + tid;
        int row = c >> 3, seg = c & 7;
        size_t src = (size_t)(b * SS + i0 + row) * DD + h * DH + seg * 8;
        uint32_t d = sb + row * 144 + seg * 16;
        cp16(d + SQ_H, g_qh + src, true);
        cp16(d + SQ_L, g_ql + src, true);
    }
    issue_kp(0);

    for (int jt = 0; jt < 16; jt++) {
        cpwait<0>();              // KP(jt) complete (V(jt) not yet issued)
        __syncthreads();          // S1: KP visible; V slot free (prev PV done)
        issue_v(jt);              // V loads overlap entire score phase
        int ub2 = (jt & 1) * 64;
        int vb2 = (jt & 1) * 128;

        float accC[2][2][4];
        float accR[2][4][4];
        #pragma unroll
        for (int a = 0; a < 2; a++) {
            #pragma unroll
            for (int c = 0; c < 2; c++)
                #pragma unroll
                for (int e = 0; e < 4; e++) accC[a][c][e] = 0.f;
            #pragma unroll
            for (int c = 0; c < 4; c++)
                #pragma unroll
                for (int e = 0; e < 4; e++) accR[a][c][e] = 0.f;
        }

        #pragma unroll
        for (int kk = 0; kk < 64; kk += 16) {
            uint32_t ah[2][4], al[2][4];
            #pragma unroll
            for (int mi = 0; mi < 2; mi++) {
                uint32_t ad = sb + SQ_H + (wm + 16 * mi + (lane & 15)) * 144
                              + (kk + ((lane >> 4) << 3)) * 2;
                ldsm4(ah[mi], ad);
                ldsm4(al[mi], ad + (SQ_L - SQ_H));
            }
            { // content: 16 cols
                int n0 = wcol * 16;
                uint32_t bd = sb + SK_H + (n0 + (lane & 15)) * 144 + (kk + ((lane >> 4) << 3)) * 2;
                uint32_t bh4[4], bl4[4];
                ldsm4(bh4, bd);
                ldsm4(bl4, bd + (SK_L - SK_H));
                #pragma unroll
                for (int half = 0; half < 2; half++) {
                    uint32_t bhh[2] = {bh4[half], bh4[half+2]};
                    uint32_t bll[2] = {bl4[half], bl4[half+2]};
                    #pragma unroll
                    for (int mi = 0; mi < 2; mi++)
                        mma3(accC[mi][half], ah[mi], al[mi], bhh, bll);
                }
            }
            #pragma unroll
            for (int nh = 0; nh < 2; nh++) { // pos: 32 cols
                int n0 = wcol * 32 + 16 * nh;
                uint32_t bd = sb + SP_H + (n0 + (lane & 15)) * 144 + (kk + ((lane >> 4) << 3)) * 2;
                uint32_t bh4[4], bl4[4];
                ldsm4(bh4, bd);
                ldsm4(bl4, bd + (SP_L - SP_H));
                #pragma unroll
                for (int half = 0; half < 2; half++) {
                    int nf = 2 * nh + half;
                    uint32_t bhh[2] = {bh4[half], bh4[half+2]};
                    uint32_t bll[2] = {bl4[half], bl4[half+2]};
                    #pragma unroll
                    for (int mi = 0; mi < 2; mi++)
                        mma3(accR[mi][nf], ah[mi], al[mi], bhh, bll);
                }
            }
        }
        // dump content + uk (own rows, own cols)
        #pragma unroll
        for (int mi = 0; mi < 2; mi++)
            #pragma unroll
            for (int nf = 0; nf < 2; nf++) {
                int jj = wcol * 16 + 8 * nf + 2 * t4;
                int rl = wm + 16 * mi + g;
                S32[rl * 68 + jj]     = (accC[mi][nf][0] + uk_s[ub2 + jj])     * SCALE;
                S32[rl * 68 + jj + 1] = (accC[mi][nf][1] + uk_s[ub2 + jj + 1]) * SCALE;
                S32[(rl + 8) * 68 + jj]     = (accC[mi][nf][2] + uk_s[ub2 + jj])     * SCALE;
                S32[(rl + 8) * 68 + jj + 1] = (accC[mi][nf][3] + uk_s[ub2 + jj + 1]) * SCALE;
            }
        __syncthreads();          // S2: K/P consumed by all; dumps visible
        if (jt < 15) issue_kp(jt + 1); else cpcommit();

        // scatter pos into OWN rows: jl = t + rl - 63
        #pragma unroll
        for (int mi = 0; mi < 2; mi++)
            #pragma unroll
            for (int nf = 0; nf < 4; nf++) {
                int t = wcol * 32 + 8 * nf + 2 * t4;
                #pragma unroll
                for (int half = 0; half < 2; half++) {
                    int rl = wm + 16 * mi + g + 8 * half;
                    int jl = t + rl - 63;
                    if (jl >= 0 && jl < 64)
                        S32[rl * 68 + jl] += (accR[mi][nf][2*half] + vp_s[vb2 + t]) * SCALE;
                    int jl2 = jl + 1;
                    if (jl2 >= 0 && jl2 < 64)
                        S32[rl * 68 + jl2] += (accR[mi][nf][2*half+1] + vp_s[vb2 + t + 1]) * SCALE;
                }
            }
        barsync(gid);             // S3 (named): group's scatters visible to group

        // ---- online softmax (4 threads per row; rows are group-local) ----
        int r = tid >> 2, q4 = tid & 3;
        float p[16];
        {
            const float4* Sp = (const float4*)(S32 + r * 68 + q4 * 16);
            float tm = -1e30f;
            #pragma unroll
            for (int q = 0; q < 4; q++) {
                float4 v = Sp[q];
                p[4*q] = v.x; p[4*q+1] = v.y; p[4*q+2] = v.z; p[4*q+3] = v.w;
                tm = fmaxf(tm, fmaxf(fmaxf(v.x, v.y), fmaxf(v.z, v.w)));
            }
            tm = fmaxf(tm, __shfl_xor_sync(0xffffffffu, tm, 1));
            tm = fmaxf(tm, __shfl_xor_sync(0xffffffffu, tm, 2));
            float mo = jt ? m_s[r] : -1e30f;
            float lo = jt ? l_s[r] : 0.f;
            float mn = fmaxf(mo, tm);
            float alpha = __expf(mo - mn);
            float sum = 0.f;
            #pragma unroll
            for (int c = 0; c < 16; c++) { p[c] = __expf(p[c] - mn); sum += p[c]; }
            sum += __shfl_xor_sync(0xffffffffu, sum, 1);
            sum += __shfl_xor_sync(0xffffffffu, sum, 2);
            if (q4 == 0) { m_s[r] = mn; l_s[r] = alpha * lo + sum; al_s[r] = alpha; }
        }
        __syncwarp();             // row's 4 threads done reading row cells

        // write probs (split bf16) row-aligned: hi @ r*272, lo @ r*272+144
        {
            uint32_t* ahp = (uint32_t*)(smem + SATT) + r * 68 + q4 * 8;
            uint32_t* alp = ahp + 36;
            #pragma unroll
            for (int q = 0; q < 8; q++) {
                uint32_t hh, ll;
                split_pair(p[2*q], p[2*q+1], hh, ll);
                ahp[q] = hh; alp[q] = ll;
            }
        }
        cpwait<1>();              // V(jt) complete (KP(jt+1) may be in flight)
        __syncthreads();          // S5: V + all prob-writes + stats visible

        // rescale O, then accumulate P @ V
        #pragma unroll
        for (int mi = 0; mi < 2; mi++) {
            float a1 = al_s[wm + 16 * mi + g];
            float a2 = al_s[wm + 16 * mi + g + 8];
            #pragma unroll
            for (int nf = 0; nf < 2; nf++) {
                accO[mi][nf][0] *= a1; accO[mi][nf][1] *= a1;
                accO[mi][nf][2] *= a2; accO[mi][nf][3] *= a2;
            }
        }
        #pragma unroll
        for (int kk = 0; kk < 64; kk += 16) {
            uint32_t ah[2][4], al[2][4];
            #pragma unroll
            for (int mi = 0; mi < 2; mi++) {
                uint32_t ad = sb + SATT + (wm + 16 * mi + (lane & 15)) * 272
                              + (kk + ((lane >> 4) << 3)) * 2;
                ldsm4(ah[mi], ad);
                ldsm4(al[mi], ad + 144);
            }
            int n0 = wcol * 16;
            uint32_t bd = sb + SV_H + (kk + (lane & 7) + (lane & 8)) * 144
                          + (n0 + ((lane & 16) >> 1)) * 2;
            uint32_t bh4[4], bl4[4];
            ldsm4t(bh4, bd);
            ldsm4t(bl4, bd + (SV_L - SV_H));
            #pragma unroll
            for (int half = 0; half < 2; half++) {
                uint32_t bhh[2] = {bh4[2*half], bh4[2*half+1]};
                uint32_t bll[2] = {bl4[2*half], bl4[2*half+1]};
                #pragma unroll
                for (int mi = 0; mi < 2; mi++)
                    mma3(accO[mi][half], ah[mi], al[mi], bhh, bll);
            }
        }
        // no S6: next iteration's S1 (CTA) guards V re-issue and S32 overwrite
    }

    __syncthreads();              // all PV reads done before epilogue reads l_s
    #pragma unroll
    for (int mi = 0; mi < 2; mi++)
        #pragma unroll
        for (int nf = 0; nf < 2; nf++)
            #pragma unroll
            for (int half = 0; half < 2; half++) {
                int rl = wm + 16 * mi + g + 8 * half;
                float inv = 1.f / l_s[rl];
                int dl = wcol * 16 + 8 * nf + 2 * t4;
                uint32_t hh, ll;
                split_pair(accO[mi][nf][2*half] * inv, accO[mi][nf][2*half+1] * inv, hh, ll);
                size_t o = (size_t)(b * SS + i0 + rl) * DD + h * DH + dl;
                *(uint32_t*)&g_ch[o] = hh;
                *(uint32_t*)&g_cl[o] = ll;
            }
}

// ---------------- launch ----------------
extern "C" void kernel_launch(void* const* d_in, const int* in_sizes, int n_in,
                              void* d_out, int out_size) {
    const float* query = (const float*)d_in[0];
    const float* key   = (const float*)d_in[1];
    const float* value = (const float*)d_in[2];
    const float* pos   = (const float*)d_in[3];
    const float* Wq    = (const float*)d_in[4];
    const float* Wk    = (const float*)d_in[5];
    const float* Wv    = (const float*)d_in[6];
    const float* Wp    = (const float*)d_in[7];
    const float* ub    = (const float*)d_in[8];
    const float* vb    = (const float*)d_in[9];
    const float* Wo    = (const float*)d_in[10];
    float* out = (float*)d_out;

    static bool attr_done = false;
    if (!attr_done) {
        cudaFuncSetAttribute(gemm_proj_all, cudaFuncAttributeMaxDynamicSharedMemorySize, G_SMEM);
        cudaFuncSetAttribute(gemm_out,      cudaFuncAttributeMaxDynamicSharedMemorySize, G_SMEM);
        cudaFuncSetAttribute(flash_v8,      cudaFuncAttributeMaxDynamicSharedMemorySize, FL_SMEM);
        attr_done = true;
    }

    dim3 blk(256);

    split_all<<<(C_W + 255)/256, blk>>>((const float4*)query, (const float4*)key,
                                        (const float4*)value, (const float4*)pos,
                                        (const float4*)Wq, (const float4*)Wk,
                                        (const float4*)Wv, (const float4*)Wp,
                                        (const float4*)Wo);

    gemm_proj_all<<<dim3(4, 320), blk, G_SMEM>>>();

    biasdot2<<<dim3((8*8*((L2P+7)/8) + 7)/8, 1, 2), blk>>>(ub, vb);

    flash_v8<<<dim3(SS/64, BB*HH), blk, FL_SMEM>>>();

    gemm_out<<<dim3(4, 64), blk, G_SMEM>>>(out);
}